// round 2
// baseline (speedup 1.0000x reference)
#include <cuda_runtime.h>

// QWT collapses: filt(x,h) = x * sum(h)  (scalar), downsample is linear.
// Every output sub-band = coef * D, D = bicubic stride-2 downsample of image.
//
// Inputs (metadata order): image (16,3,512,512) f32, gl, gh, fl, fh (30 f32 each)
// Output: concat of 4 tensors, each (16,12,256,256) f32.

#define W0 (-0.09375f)
#define W1 ( 0.59375f)
#define W2 ( 0.59375f)
#define W3 (-0.09375f)

__device__ float g_coef[16];

__global__ void coef_kernel(const float* __restrict__ gl, const float* __restrict__ gh,
                            const float* __restrict__ fl, const float* __restrict__ fh) {
    if (threadIdx.x == 0) {
        float A = 0.f, B = 0.f, C = 0.f, D = 0.f;
        for (int k = 0; k < 30; k++) { A += gl[k]; B += gh[k]; C += fl[k]; D += fh[k]; }
        // coef[t*4+q]:
        //  first factor (downsampled branch): t<2 ? (q&1 ? C : A) : (q&1 ? D : B)
        //  second factor (post filter):       (t&1)==0 ? (q&2 ? C : A) : (q&2 ? D : B)
        for (int t = 0; t < 4; t++) {
            for (int q = 0; q < 4; q++) {
                float f1 = (t < 2) ? ((q & 1) ? C : A) : ((q & 1) ? D : B);
                float f2 = ((t & 1) == 0) ? ((q & 2) ? C : A) : ((q & 2) ? D : B);
                g_coef[t * 4 + q] = f1 * f2;
            }
        }
    }
}

// Block: (64,4) threads. Thread handles 4 consecutive output cols (float4 stores).
// Grid: (1, 64, 48)  -> 48 = batch*channels images of 512x512.
__global__ __launch_bounds__(256) void qwt_down_kernel(const float* __restrict__ img,
                                                       float* __restrict__ out) {
    const int j0      = threadIdx.x * 4;                 // output col base (0..252)
    const int i       = blockIdx.y * 4 + threadIdx.y;    // output row (0..255)
    const int img_idx = blockIdx.z;                      // b*3 + c

    __shared__ float sc[16];
    if (threadIdx.y == 0 && threadIdx.x < 16) sc[threadIdx.x] = g_coef[threadIdx.x];
    __syncthreads();

    const float* src = img + (size_t)img_idx * 512 * 512;

    // 4 source rows, edge-clamped
    int r0 = max(0, 2 * i - 1);
    int r1 = 2 * i;
    int r2 = 2 * i + 1;
    int r3 = min(511, 2 * i + 2);
    const float* p0 = src + (size_t)r0 * 512;
    const float* p1 = src + (size_t)r1 * 512;
    const float* p2 = src + (size_t)r2 * 512;
    const float* p3 = src + (size_t)r3 * 512;

    // Vertical pass over the 10 source columns covering 4 outputs
    float v[10];
#pragma unroll
    for (int q = 0; q < 10; q++) {
        int col = 2 * j0 - 1 + q;
        col = max(0, min(511, col));
        v[q] = W0 * p0[col] + W1 * p1[col] + W2 * p2[col] + W3 * p3[col];
    }

    // Horizontal pass: 4 downsampled values
    float d0 = W0 * v[0] + W1 * v[1] + W2 * v[2] + W3 * v[3];
    float d1 = W0 * v[2] + W1 * v[3] + W2 * v[4] + W3 * v[5];
    float d2 = W0 * v[4] + W1 * v[5] + W2 * v[6] + W3 * v[7];
    float d3 = W0 * v[6] + W1 * v[7] + W2 * v[8] + W3 * v[9];

    const int b = img_idx / 3;
    const int c = img_idx % 3;
    const size_t tensor_sz = (size_t)16 * 12 * 256 * 256;

#pragma unroll
    for (int t = 0; t < 4; t++) {
#pragma unroll
        for (int q = 0; q < 4; q++) {
            float s = sc[t * 4 + q];
            float4 o = make_float4(s * d0, s * d1, s * d2, s * d3);
            size_t idx = (size_t)t * tensor_sz +
                         ((size_t)((b * 12 + q * 3 + c) * 256 + i)) * 256 + j0;
            *reinterpret_cast<float4*>(out + idx) = o;
        }
    }
}

extern "C" void kernel_launch(void* const* d_in, const int* in_sizes, int n_in,
                              void* d_out, int out_size) {
    const float* image = (const float*)d_in[0];
    const float* gl    = (const float*)d_in[1];
    const float* gh    = (const float*)d_in[2];
    const float* fl    = (const float*)d_in[3];
    const float* fh    = (const float*)d_in[4];
    float* out = (float*)d_out;

    coef_kernel<<<1, 32>>>(gl, gh, fl, fh);

    dim3 block(64, 4, 1);
    dim3 grid(1, 64, 48);
    qwt_down_kernel<<<grid, block>>>(image, out);
}